// round 6
// baseline (speedup 1.0000x reference)
#include <cuda_runtime.h>
#include <cuda_bf16.h>

// EdgeMLP: out = silu( silu( LN( [src|edge] @ W1 + b1 ) ) @ W2 + b2 )
// E=500000, NODE=128, EDGE=64, IN=192, OUT=128, fp32.
//
// v3: 512 threads (4 warps/SMSP), 4x8 per-thread micro-tile, register
// double-buffered x-operand, packed fma.rn.f32x2. Weights persistent in SMEM.

static constexpr int NODE_DIM = 128;
static constexpr int EDGE_DIM = 64;
static constexpr int OUT_DIM  = 128;

static constexpr int BR      = 128;   // rows per tile
static constexpr int THREADS = 512;

// shared memory layout (float offsets)
static constexpr int OFF_W1  = 0;                          // 192*128
static constexpr int OFF_W2  = OFF_W1 + 192 * OUT_DIM;     // 128*128
static constexpr int OFF_B1  = OFF_W2 + OUT_DIM * OUT_DIM;
static constexpr int OFF_B2  = OFF_B1 + OUT_DIM;
static constexpr int OFF_G   = OFF_B2 + OUT_DIM;
static constexpr int OFF_BT  = OFF_G  + OUT_DIM;
static constexpr int OFF_BUF = OFF_BT + OUT_DIM;           // 128*128 floats (X chunk / H)
static constexpr int SMEM_FLOATS = OFF_BUF + BR * 128;
static constexpr int SMEM_BYTES  = SMEM_FLOATS * 4;        // 231424 B <= 232448 limit

typedef unsigned long long ull;

// ---------- packed fp32x2 helpers ----------
__device__ __forceinline__ ull ffma2(ull a, ull b, ull c) {
    ull d;
    asm("fma.rn.f32x2 %0, %1, %2, %3;" : "=l"(d) : "l"(a), "l"(b), "l"(c));
    return d;
}
__device__ __forceinline__ ull dup2(float x) {
    ull r;
    asm("mov.b64 %0, {%1, %1};" : "=l"(r) : "f"(x));
    return r;
}
__device__ __forceinline__ float2 unpack2(ull v) {
    float2 f;
    asm("mov.b64 {%0, %1}, %2;" : "=f"(f.x), "=f"(f.y) : "l"(v));
    return f;
}
__device__ __forceinline__ float silu_f(float y) {
    return __fdividef(y, 1.0f + __expf(-y));   // rel err ~2e-6 << 1e-3
}

// ---------- bias broadcast into accumulators ----------
__device__ __forceinline__ void acc_init(const float* __restrict__ sB, int c0,
                                         ull acc[4][4]) {
#pragma unroll
    for (int p = 0; p < 4; p++) {
        ull bp = *(const ull*)(sB + c0 + 2 * p);
#pragma unroll
        for (int i = 0; i < 4; i++) acc[i][p] = bp;
    }
}

// ---------- register-tiled GEMM accumulate over SMEM operands ----------
// acc[4 rows][4 col-pairs] += sA[r0..r0+3][0:KC] @ sW[0:KC][c0..c0+7]
// AS = row stride of sA (floats, multiple of 4). x is double-buffered in
// registers so the LDS latency of the next k-block hides under this block's
// FFMA2 stream.
template <int KC, int AS>
__device__ __forceinline__ void gemm_acc(const float* __restrict__ sA,
                                         const float* __restrict__ sW,
                                         int r0, int c0, ull acc[4][4]) {
    constexpr int NKB = KC / 4;
    float4 xa[2][4];
#pragma unroll
    for (int i = 0; i < 4; i++)
        xa[0][i] = *(const float4*)(sA + (r0 + i) * AS);

#pragma unroll 2
    for (int kb = 0; kb < NKB; kb++) {
        const int cur = kb & 1;
        if (kb + 1 < NKB) {
#pragma unroll
            for (int i = 0; i < 4; i++)
                xa[cur ^ 1][i] = *(const float4*)(sA + (r0 + i) * AS + (kb + 1) * 4);
        }
#pragma unroll
        for (int kk = 0; kk < 4; kk++) {
            const int k = kb * 4 + kk;
            const ulonglong2 wa = *(const ulonglong2*)(sW + k * OUT_DIM + c0);
            const ulonglong2 wb = *(const ulonglong2*)(sW + k * OUT_DIM + c0 + 4);
            const ull w0 = wa.x, w1 = wa.y, w2 = wb.x, w3 = wb.y;
#pragma unroll
            for (int i = 0; i < 4; i++) {
                const float xs = (kk == 0) ? xa[cur][i].x
                               : (kk == 1) ? xa[cur][i].y
                               : (kk == 2) ? xa[cur][i].z : xa[cur][i].w;
                const ull a = dup2(xs);
                acc[i][0] = ffma2(a, w0, acc[i][0]);
                acc[i][1] = ffma2(a, w1, acc[i][1]);
                acc[i][2] = ffma2(a, w2, acc[i][2]);
                acc[i][3] = ffma2(a, w3, acc[i][3]);
            }
        }
    }
}

__global__ void __launch_bounds__(THREADS, 1)
edge_mlp_kernel(const float* __restrict__ src, const float* __restrict__ edg,
                const float* __restrict__ W1,  const float* __restrict__ b1,
                const float* __restrict__ gam, const float* __restrict__ bet,
                const float* __restrict__ W2,  const float* __restrict__ b2,
                float* __restrict__ out, int E, int ntiles) {
    extern __shared__ float sm[];
    float* sW1  = sm + OFF_W1;
    float* sW2  = sm + OFF_W2;
    float* sB1  = sm + OFF_B1;
    float* sB2  = sm + OFF_B2;
    float* sG   = sm + OFF_G;
    float* sBt  = sm + OFF_BT;
    float* sBuf = sm + OFF_BUF;

    const int tid = threadIdx.x;

    // One-time weight/bias preload (persistent CTA).
    for (int i = tid; i < 192 * OUT_DIM; i += THREADS) sW1[i] = W1[i];
    for (int i = tid; i < OUT_DIM * OUT_DIM; i += THREADS) sW2[i] = W2[i];
    if (tid < OUT_DIM) {
        sB1[tid] = b1[tid];
        sB2[tid] = b2[tid];
        sG[tid]  = gam[tid];
        sBt[tid] = bet[tid];
    }

    const int cg = tid & 15;          // cols 8*cg .. 8*cg+7
    const int rg = tid >> 4;          // rows 4*rg .. 4*rg+3
    const int r0 = rg * 4, c0 = cg * 8;
    const int warp = tid >> 5, lane = tid & 31;

    for (int tile = blockIdx.x; tile < ntiles; tile += gridDim.x) {
        const int rowbase = tile * BR;
        const bool full = (rowbase + BR <= E);

        __syncthreads();   // sBuf free (covers preload on iter 0 too)

        // ---- stage src chunk: 128 x 128, contiguous float4 copy ----
        {
            float4* d4 = (float4*)sBuf;
            const int n4 = BR * NODE_DIM / 4;
            if (full) {
                const float4* s4 = (const float4*)(src + (size_t)rowbase * NODE_DIM);
#pragma unroll
                for (int j = 0; j < n4 / THREADS; j++)
                    d4[tid + j * THREADS] = s4[tid + j * THREADS];
            } else {
                for (int i = tid; i < n4; i += THREADS) {
                    const int r = i / (NODE_DIM / 4);
                    float4 v = make_float4(0.f, 0.f, 0.f, 0.f);
                    if (rowbase + r < E)
                        v = ((const float4*)(src + (size_t)rowbase * NODE_DIM))[i];
                    d4[i] = v;
                }
            }
        }
        __syncthreads();

        // ---- GEMM1 part A: src @ W1[0:128] + b1 ----
        ull acc[4][4];
        acc_init(sB1, c0, acc);
        gemm_acc<NODE_DIM, 128>(sBuf, sW1, r0, c0, acc);
        __syncthreads();   // done reading src chunk

        // ---- stage edge chunk: 128 x 64, contiguous float4 copy ----
        {
            float4* d4 = (float4*)sBuf;
            const int n4 = BR * EDGE_DIM / 4;
            if (full) {
                const float4* s4 = (const float4*)(edg + (size_t)rowbase * EDGE_DIM);
#pragma unroll
                for (int j = 0; j < n4 / THREADS; j++)
                    d4[tid + j * THREADS] = s4[tid + j * THREADS];
            } else {
                for (int i = tid; i < n4; i += THREADS) {
                    const int r = i / (EDGE_DIM / 4);
                    float4 v = make_float4(0.f, 0.f, 0.f, 0.f);
                    if (rowbase + r < E)
                        v = ((const float4*)(edg + (size_t)rowbase * EDGE_DIM))[i];
                    d4[i] = v;
                }
            }
        }
        __syncthreads();

        // ---- GEMM1 part B: edge @ W1[128:192] ----
        gemm_acc<EDGE_DIM, 64>(sBuf, sW1 + NODE_DIM * OUT_DIM, r0, c0, acc);
        __syncthreads();   // done reading edge chunk; sBuf becomes H

        // ---- spill H (stride 128) ----
#pragma unroll
        for (int i = 0; i < 4; i++) {
            ull* dst = (ull*)(sBuf + (r0 + i) * 128 + c0);
            dst[0] = acc[i][0];
            dst[1] = acc[i][1];
            dst[2] = acc[i][2];
            dst[3] = acc[i][3];
        }
        __syncthreads();

        // ---- LayerNorm + SiLU in place: warp = 8 rows ----
        for (int rr = 0; rr < 8; rr++) {
            const int r = warp * 8 + rr;
            float v0 = sBuf[r * 128 + lane];
            float v1 = sBuf[r * 128 + lane + 32];
            float v2 = sBuf[r * 128 + lane + 64];
            float v3 = sBuf[r * 128 + lane + 96];
            float s = v0 + v1 + v2 + v3;
#pragma unroll
            for (int o = 16; o > 0; o >>= 1) s += __shfl_xor_sync(0xffffffffu, s, o);
            const float mu = s * (1.0f / 128.0f);
            const float d0 = v0 - mu, d1 = v1 - mu, d2 = v2 - mu, d3 = v3 - mu;
            float q = d0 * d0 + d1 * d1 + d2 * d2 + d3 * d3;
#pragma unroll
            for (int o = 16; o > 0; o >>= 1) q += __shfl_xor_sync(0xffffffffu, q, o);
            const float rs = rsqrtf(q * (1.0f / 128.0f) + 1e-5f);
            sBuf[r * 128 + lane]      = silu_f(d0 * rs * sG[lane]      + sBt[lane]);
            sBuf[r * 128 + lane + 32] = silu_f(d1 * rs * sG[lane + 32] + sBt[lane + 32]);
            sBuf[r * 128 + lane + 64] = silu_f(d2 * rs * sG[lane + 64] + sBt[lane + 64]);
            sBuf[r * 128 + lane + 96] = silu_f(d3 * rs * sG[lane + 96] + sBt[lane + 96]);
        }
        __syncthreads();

        // ---- GEMM2: H @ W2 + b2 ----
        acc_init(sB2, c0, acc);
        gemm_acc<OUT_DIM, 128>(sBuf, sW2, r0, c0, acc);

        // ---- epilogue: SiLU + vectorized store ----
#pragma unroll
        for (int i = 0; i < 4; i++) {
            const int row = rowbase + r0 + i;
            if (row < E) {
                float o[8];
#pragma unroll
                for (int p = 0; p < 4; p++) {
                    float2 v = unpack2(acc[i][p]);
                    o[2 * p]     = silu_f(v.x);
                    o[2 * p + 1] = silu_f(v.y);
                }
                float4* dst = (float4*)(out + (size_t)row * OUT_DIM + c0);
                dst[0] = make_float4(o[0], o[1], o[2], o[3]);
                dst[1] = make_float4(o[4], o[5], o[6], o[7]);
            }
        }
        // top-of-loop sync protects sBuf before next restage
    }
}

extern "C" void kernel_launch(void* const* d_in, const int* in_sizes, int n_in,
                              void* d_out, int out_size) {
    const float* src = (const float*)d_in[0];
    const float* edg = (const float*)d_in[1];
    const float* W1  = (const float*)d_in[2];
    const float* b1  = (const float*)d_in[3];
    const float* gam = (const float*)d_in[4];
    const float* bet = (const float*)d_in[5];
    const float* W2  = (const float*)d_in[6];
    const float* b2  = (const float*)d_in[7];
    float* out = (float*)d_out;

    const int E = in_sizes[0] / NODE_DIM;
    const int ntiles = (E + BR - 1) / BR;

    cudaFuncSetAttribute(edge_mlp_kernel,
                         cudaFuncAttributeMaxDynamicSharedMemorySize, SMEM_BYTES);

    int nsm = 148;
    if (cudaDeviceGetAttribute(&nsm, cudaDevAttrMultiProcessorCount, 0) != cudaSuccess
        || nsm <= 0)
        nsm = 148;
    int grid = nsm < ntiles ? nsm : ntiles;

    edge_mlp_kernel<<<grid, THREADS, SMEM_BYTES>>>(src, edg, W1, b1, gam, bet,
                                                   W2, b2, out, E, ntiles);
}

// round 7
// speedup vs baseline: 1.4463x; 1.4463x over previous
#include <cuda_runtime.h>
#include <cuda_bf16.h>

// EdgeMLP: out = silu( silu( LN( [src|edge] @ W1 + b1 ) ) @ W2 + b2 )
// E=500000, NODE=128, EDGE=64, IN=192, OUT=128, fp32.
//
// v4: 512 threads. Warp owns a 32-row x 32-col block (thread = 4x8), so each
// warp reads only 128 contiguous bytes of W per k (conflict-free) instead of
// the whole 512B row 4-way conflicted. X/H live in a chunk-swizzled SMEM
// buffer (16B chunk ^ ((row>>2)&7)) making the strided float4 x loads
// conflict-free. Packed fma.rn.f32x2 accumulators; weights persistent in SMEM.

static constexpr int NODE_DIM = 128;
static constexpr int EDGE_DIM = 64;
static constexpr int OUT_DIM  = 128;

static constexpr int BR      = 128;   // rows per tile
static constexpr int THREADS = 512;

// shared memory layout (float offsets)
static constexpr int OFF_W1  = 0;                          // 192*128
static constexpr int OFF_W2  = OFF_W1 + 192 * OUT_DIM;     // 128*128
static constexpr int OFF_B1  = OFF_W2 + OUT_DIM * OUT_DIM;
static constexpr int OFF_B2  = OFF_B1 + OUT_DIM;
static constexpr int OFF_G   = OFF_B2 + OUT_DIM;
static constexpr int OFF_BT  = OFF_G  + OUT_DIM;
static constexpr int OFF_BUF = OFF_BT + OUT_DIM;           // 128*128 floats (X chunk / H)
static constexpr int SMEM_FLOATS = OFF_BUF + BR * 128;
static constexpr int SMEM_BYTES  = SMEM_FLOATS * 4;        // 231424 B <= 232448 limit

typedef unsigned long long ull;

// ---------- packed fp32x2 helpers ----------
__device__ __forceinline__ ull ffma2(ull a, ull b, ull c) {
    ull d;
    asm("fma.rn.f32x2 %0, %1, %2, %3;" : "=l"(d) : "l"(a), "l"(b), "l"(c));
    return d;
}
__device__ __forceinline__ ull dup2(float x) {
    ull r;
    asm("mov.b64 %0, {%1, %1};" : "=l"(r) : "f"(x));
    return r;
}
__device__ __forceinline__ float2 unpack2(ull v) {
    float2 f;
    asm("mov.b64 {%0, %1}, %2;" : "=f"(f.x), "=f"(f.y) : "l"(v));
    return f;
}
__device__ __forceinline__ float silu_f(float y) {
    return __fdividef(y, 1.0f + __expf(-y));   // rel err ~2e-6 << 1e-3
}

// ---------- bias broadcast into accumulators ----------
__device__ __forceinline__ void acc_init(const float* __restrict__ sB, int c0,
                                         ull acc[4][4]) {
#pragma unroll
    for (int p = 0; p < 4; p++) {
        ull bp = *(const ull*)(sB + c0 + 2 * p);
#pragma unroll
        for (int i = 0; i < 4; i++) acc[i][p] = bp;
    }
}

// ---------- register-tiled GEMM accumulate (swizzled A, row-major W) ----------
// acc[4 rows][4 col-pairs] += A[rloc..rloc+3][0:KC] @ sW[0:KC][c0..c0+7]
// A is stored swizzled: float4 chunk kb of row r lives at (r*ASC + (kb^s))*4,
// s = (r>>2)&7 (constant across the thread's 4 rows since rloc % 4 == 0).
template <int KC, int ASC>
__device__ __forceinline__ void gemm_acc(const float* __restrict__ sA,
                                         const float* __restrict__ sW,
                                         int rloc, int c0, ull acc[4][4]) {
    constexpr int NKB = KC / 4;
    const int s = (rloc >> 2) & 7;
    const float* a0 = sA + (rloc + 0) * (ASC * 4);
    const float* a1 = sA + (rloc + 1) * (ASC * 4);
    const float* a2 = sA + (rloc + 2) * (ASC * 4);
    const float* a3 = sA + (rloc + 3) * (ASC * 4);

    float4 xa[2][4];
    xa[0][0] = *(const float4*)(a0 + ((0 ^ s) << 2));
    xa[0][1] = *(const float4*)(a1 + ((0 ^ s) << 2));
    xa[0][2] = *(const float4*)(a2 + ((0 ^ s) << 2));
    xa[0][3] = *(const float4*)(a3 + ((0 ^ s) << 2));

#pragma unroll 2
    for (int kb = 0; kb < NKB; kb++) {
        const int cur = kb & 1;
        if (kb + 1 < NKB) {
            const int nc = ((kb + 1) ^ s) << 2;
            xa[cur ^ 1][0] = *(const float4*)(a0 + nc);
            xa[cur ^ 1][1] = *(const float4*)(a1 + nc);
            xa[cur ^ 1][2] = *(const float4*)(a2 + nc);
            xa[cur ^ 1][3] = *(const float4*)(a3 + nc);
        }
#pragma unroll
        for (int kk = 0; kk < 4; kk++) {
            const int k = kb * 4 + kk;
            const ulonglong2 wa = *(const ulonglong2*)(sW + k * OUT_DIM + c0);
            const ulonglong2 wb = *(const ulonglong2*)(sW + k * OUT_DIM + c0 + 4);
            const ull w0 = wa.x, w1 = wa.y, w2 = wb.x, w3 = wb.y;
#pragma unroll
            for (int i = 0; i < 4; i++) {
                const float xs = (kk == 0) ? xa[cur][i].x
                               : (kk == 1) ? xa[cur][i].y
                               : (kk == 2) ? xa[cur][i].z : xa[cur][i].w;
                const ull a = dup2(xs);
                acc[i][0] = ffma2(a, w0, acc[i][0]);
                acc[i][1] = ffma2(a, w1, acc[i][1]);
                acc[i][2] = ffma2(a, w2, acc[i][2]);
                acc[i][3] = ffma2(a, w3, acc[i][3]);
            }
        }
    }
}

__global__ void __launch_bounds__(THREADS, 1)
edge_mlp_kernel(const float* __restrict__ src, const float* __restrict__ edg,
                const float* __restrict__ W1,  const float* __restrict__ b1,
                const float* __restrict__ gam, const float* __restrict__ bet,
                const float* __restrict__ W2,  const float* __restrict__ b2,
                float* __restrict__ out, int E, int ntiles) {
    extern __shared__ float sm[];
    float* sW1  = sm + OFF_W1;
    float* sW2  = sm + OFF_W2;
    float* sB1  = sm + OFF_B1;
    float* sB2  = sm + OFF_B2;
    float* sG   = sm + OFF_G;
    float* sBt  = sm + OFF_BT;
    float* sBuf = sm + OFF_BUF;

    const int tid = threadIdx.x;

    // One-time weight/bias preload (persistent CTA).
    for (int i = tid; i < 192 * OUT_DIM; i += THREADS) sW1[i] = W1[i];
    for (int i = tid; i < OUT_DIM * OUT_DIM; i += THREADS) sW2[i] = W2[i];
    if (tid < OUT_DIM) {
        sB1[tid] = b1[tid];
        sB2[tid] = b2[tid];
        sG[tid]  = gam[tid];
        sBt[tid] = bet[tid];
    }

    // warp block mapping: warp = 32 rows x 32 cols; thread = 4 rows x 8 cols
    const int warp = tid >> 5, lane = tid & 31;
    const int cgl  = lane & 3;          // col sub-group within warp
    const int rg   = lane >> 2;         // row sub-group within warp (0..7)
    const int rloc = ((warp >> 2) << 5) + (rg << 2);   // local row base (mult of 4)
    const int c0   = ((warp & 3) << 5) + (cgl << 3);   // col base (8 cols)
    const int sthr = (rloc >> 2) & 7;                  // this thread's swizzle

    for (int tile = blockIdx.x; tile < ntiles; tile += gridDim.x) {
        const int rowbase = tile * BR;
        const bool full = (rowbase + BR <= E);

        __syncthreads();   // sBuf free (covers preload on iter 0 too)

        // ---- stage src chunk: 128 rows x 32 chunks(16B), swizzled ----
        {
            float4* d4 = (float4*)sBuf;
            const float4* s4 = (const float4*)(src + (size_t)rowbase * NODE_DIM);
            constexpr int N4 = BR * (NODE_DIM / 4);   // 4096
#pragma unroll
            for (int j = 0; j < N4 / THREADS; j++) {
                const int i = tid + j * THREADS;
                const int r = i >> 5, c = i & 31;
                float4 v = make_float4(0.f, 0.f, 0.f, 0.f);
                if (full || rowbase + r < E) v = s4[i];
                d4[(r << 5) + (c ^ ((r >> 2) & 7))] = v;
            }
        }
        __syncthreads();

        // ---- GEMM1 part A: src @ W1[0:128] + b1 ----
        ull acc[4][4];
        acc_init(sB1, c0, acc);
        gemm_acc<NODE_DIM, 32>(sBuf, sW1, rloc, c0, acc);
        __syncthreads();   // done reading src chunk

        // ---- stage edge chunk: 128 rows x 16 chunks(16B), swizzled ----
        {
            float4* d4 = (float4*)sBuf;
            const float4* s4 = (const float4*)(edg + (size_t)rowbase * EDGE_DIM);
            constexpr int N4 = BR * (EDGE_DIM / 4);   // 2048
#pragma unroll
            for (int j = 0; j < N4 / THREADS; j++) {
                const int i = tid + j * THREADS;
                const int r = i >> 4, c = i & 15;
                float4 v = make_float4(0.f, 0.f, 0.f, 0.f);
                if (full || rowbase + r < E) v = s4[i];
                d4[(r << 4) + (c ^ ((r >> 2) & 7))] = v;
            }
        }
        __syncthreads();

        // ---- GEMM1 part B: edge @ W1[128:192] ----
        gemm_acc<EDGE_DIM, 16>(sBuf, sW1 + NODE_DIM * OUT_DIM, rloc, c0, acc);
        __syncthreads();   // done reading edge chunk; sBuf becomes H

        // ---- spill H (swizzled, 32 chunks/row) ----
#pragma unroll
        for (int i = 0; i < 4; i++) {
            const int rb = (rloc + i) << 5;
            const int ch = c0 >> 2;   // 2*cg
            float2 v0 = unpack2(acc[i][0]), v1 = unpack2(acc[i][1]);
            float2 v2 = unpack2(acc[i][2]), v3 = unpack2(acc[i][3]);
            ((float4*)sBuf)[rb + (ch ^ sthr)]       = make_float4(v0.x, v0.y, v1.x, v1.y);
            ((float4*)sBuf)[rb + ((ch + 1) ^ sthr)] = make_float4(v2.x, v2.y, v3.x, v3.y);
        }
        __syncthreads();

        // ---- LayerNorm + SiLU in place: warp = 8 rows ----
        for (int rr = 0; rr < 8; rr++) {
            const int r = (warp << 3) + rr;
            const int sr = (r >> 2) & 7;
            const int base = r << 7;
            const int lq = lane >> 2, lm = lane & 3;
            const int o0 = base + (((lq + 0)  ^ sr) << 2) + lm;   // col lane
            const int o1 = base + (((lq + 8)  ^ sr) << 2) + lm;   // col lane+32
            const int o2 = base + (((lq + 16) ^ sr) << 2) + lm;   // col lane+64
            const int o3 = base + (((lq + 24) ^ sr) << 2) + lm;   // col lane+96
            float v0 = sBuf[o0], v1 = sBuf[o1], v2 = sBuf[o2], v3 = sBuf[o3];
            float s = v0 + v1 + v2 + v3;
#pragma unroll
            for (int o = 16; o > 0; o >>= 1) s += __shfl_xor_sync(0xffffffffu, s, o);
            const float mu = s * (1.0f / 128.0f);
            const float d0 = v0 - mu, d1 = v1 - mu, d2 = v2 - mu, d3 = v3 - mu;
            float q = d0 * d0 + d1 * d1 + d2 * d2 + d3 * d3;
#pragma unroll
            for (int o = 16; o > 0; o >>= 1) q += __shfl_xor_sync(0xffffffffu, q, o);
            const float rs = rsqrtf(q * (1.0f / 128.0f) + 1e-5f);
            sBuf[o0] = silu_f(d0 * rs * sG[lane]      + sBt[lane]);
            sBuf[o1] = silu_f(d1 * rs * sG[lane + 32] + sBt[lane + 32]);
            sBuf[o2] = silu_f(d2 * rs * sG[lane + 64] + sBt[lane + 64]);
            sBuf[o3] = silu_f(d3 * rs * sG[lane + 96] + sBt[lane + 96]);
        }
        __syncthreads();

        // ---- GEMM2: H @ W2 + b2 ----
        acc_init(sB2, c0, acc);
        gemm_acc<OUT_DIM, 32>(sBuf, sW2, rloc, c0, acc);

        // ---- epilogue: SiLU + vectorized store ----
#pragma unroll
        for (int i = 0; i < 4; i++) {
            const int row = rowbase + rloc + i;
            if (row < E) {
                float o[8];
#pragma unroll
                for (int p = 0; p < 4; p++) {
                    float2 v = unpack2(acc[i][p]);
                    o[2 * p]     = silu_f(v.x);
                    o[2 * p + 1] = silu_f(v.y);
                }
                float4* dst = (float4*)(out + (size_t)row * OUT_DIM + c0);
                dst[0] = make_float4(o[0], o[1], o[2], o[3]);
                dst[1] = make_float4(o[4], o[5], o[6], o[7]);
            }
        }
        // top-of-loop sync protects sBuf before next restage
    }
}

extern "C" void kernel_launch(void* const* d_in, const int* in_sizes, int n_in,
                              void* d_out, int out_size) {
    const float* src = (const float*)d_in[0];
    const float* edg = (const float*)d_in[1];
    const float* W1  = (const float*)d_in[2];
    const float* b1  = (const float*)d_in[3];
    const float* gam = (const float*)d_in[4];
    const float* bet = (const float*)d_in[5];
    const float* W2  = (const float*)d_in[6];
    const float* b2  = (const float*)d_in[7];
    float* out = (float*)d_out;

    const int E = in_sizes[0] / NODE_DIM;
    const int ntiles = (E + BR - 1) / BR;

    cudaFuncSetAttribute(edge_mlp_kernel,
                         cudaFuncAttributeMaxDynamicSharedMemorySize, SMEM_BYTES);

    int nsm = 148;
    if (cudaDeviceGetAttribute(&nsm, cudaDevAttrMultiProcessorCount, 0) != cudaSuccess
        || nsm <= 0)
        nsm = 148;
    int grid = nsm < ntiles ? nsm : ntiles;

    edge_mlp_kernel<<<grid, THREADS, SMEM_BYTES>>>(src, edg, W1, b1, gam, bet,
                                                   W2, b2, out, E, ntiles);
}

// round 9
// speedup vs baseline: 3.1479x; 2.1766x over previous
#include <cuda_runtime.h>
#include <cuda_bf16.h>

// EdgeMLP via split-bf16 warp-level MMA (mma.sync m16n8k16, bf16->f32).
// out = silu( silu( LN( [src|edge] @ W1 + b1 ) ) @ W2 + b2 ), fp32 I/O.
// x = xh + xl (bf16 each); x*w ~= xh*wh + xh*wl + xl*wh (error ~2^-16).
// NOTE: tcgen05 is unavailable (harness PTX targets sm_103 without 'a');
// mma.sync/ldmatrix are baseline PTX ISA and still run on the tensor pipe.

typedef unsigned int u32;
typedef unsigned short u16;
typedef unsigned long long u64;

static constexpr int THREADS = 512;
static constexpr int BR = 128, NODE = 128, EDGED = 64, OUTD = 128;

// ---- smem byte offsets ----
static constexpr int OFF_W1AH = 0;        // W1 k<128:  [n=128][k=128] bf16 hi
static constexpr int OFF_W1AL = 32768;
static constexpr int OFF_W1BH = 65536;    // W1 k>=128: [128][64]
static constexpr int OFF_W1BL = 81920;
static constexpr int OFF_W2H  = 98304;    // [128][128]
static constexpr int OFF_W2L  = 131072;
static constexpr int OFF_BUFH = 163840;   // X/H hi [128][128] (edge uses [128][64]);
static constexpr int OFF_BUFL = 196608;   //   first 4KB doubles as LN partials
static constexpr int OFF_B1 = 229376, OFF_B2 = 229888;
static constexpr int OFF_G  = 230400, OFF_BT = 230912;
static constexpr int SMEM_BYTES = 231424; // <= 232448

__device__ __forceinline__ u32 smem_u32(const void* p) {
    u32 a;
    asm("{ .reg .u64 t; cvta.to.shared.u64 t, %1; cvt.u32.u64 %0, t; }"
        : "=r"(a) : "l"(p));
    return a;
}
__device__ __forceinline__ float silu_f(float y) {
    return __fdividef(y, 1.0f + __expf(-y));
}
__device__ __forceinline__ void split2(float v, u16& h, u16& l) {
    __nv_bfloat16 hb = __float2bfloat16(v);
    h = __bfloat16_as_ushort(hb);
    l = __bfloat16_as_ushort(__float2bfloat16(v - __bfloat162float(hb)));
}

// byte address of 16B chunk holding (row, k) in a [rows][NC*8 k] bf16 tile,
// chunk-swizzled: chunk ^ (row & 7)  -> ldmatrix phases are conflict-free.
template <int NC>
__device__ __forceinline__ u32 fr_addr(u32 base, int row, int k) {
    return base + (((row * NC) + ((k >> 3) ^ (row & 7))) << 4);
}

#define LDSM4(R0, R1, R2, R3, A)                                          \
    asm volatile("ldmatrix.sync.aligned.m8n8.x4.shared.b16 {%0,%1,%2,%3}, [%4];" \
                 : "=r"(R0), "=r"(R1), "=r"(R2), "=r"(R3) : "r"(A))

__device__ __forceinline__ void mma_bf16(float* c, u32 a0, u32 a1, u32 a2, u32 a3,
                                         u32 b0, u32 b1) {
    asm volatile(
        "mma.sync.aligned.m16n8k16.row.col.f32.bf16.bf16.f32 "
        "{%0,%1,%2,%3}, {%4,%5,%6,%7}, {%8,%9}, {%0,%1,%2,%3};"
        : "+f"(c[0]), "+f"(c[1]), "+f"(c[2]), "+f"(c[3])
        : "r"(a0), "r"(a1), "r"(a2), "r"(a3), "r"(b0), "r"(b1));
}

// One k16 step: acc[2 mtiles][4 ntiles][4] += A(32xk16) x B(k16x32), 3 split terms.
template <int NCA, int NCB>
__device__ __forceinline__ void k_step(u32 aH, u32 aL, u32 bH, u32 bL,
                                       int wm, int wn, int k0,
                                       float acc[2][4][4], int lane) {
    const int la7 = lane & 7;
    const int arow = wm * 32 + la7 + (((lane >> 3) & 1) << 3);
    const int ak   = k0 + ((lane >> 4) << 3);
    const int brow = wn * 32 + la7 + ((lane >> 4) << 3);
    const int bk   = k0 + (((lane >> 3) & 1) << 3);

    u32 ah[8], al[8], bh[8], bl[8];
    LDSM4(ah[0], ah[1], ah[2], ah[3], fr_addr<NCA>(aH, arow, ak));
    LDSM4(ah[4], ah[5], ah[6], ah[7], fr_addr<NCA>(aH, arow + 16, ak));
    LDSM4(al[0], al[1], al[2], al[3], fr_addr<NCA>(aL, arow, ak));
    LDSM4(al[4], al[5], al[6], al[7], fr_addr<NCA>(aL, arow + 16, ak));
    LDSM4(bh[0], bh[1], bh[2], bh[3], fr_addr<NCB>(bH, brow, bk));
    LDSM4(bh[4], bh[5], bh[6], bh[7], fr_addr<NCB>(bH, brow + 16, bk));
    LDSM4(bl[0], bl[1], bl[2], bl[3], fr_addr<NCB>(bL, brow, bk));
    LDSM4(bl[4], bl[5], bl[6], bl[7], fr_addr<NCB>(bL, brow + 16, bk));

#pragma unroll
    for (int mt = 0; mt < 2; mt++) {
        const u32* Ah = ah + 4 * mt;
        const u32* Al = al + 4 * mt;
#pragma unroll
        for (int nt = 0; nt < 4; nt++) {
            const u32 B0h = bh[2 * nt], B1h = bh[2 * nt + 1];
            const u32 B0l = bl[2 * nt], B1l = bl[2 * nt + 1];
            float* C = acc[mt][nt];
            mma_bf16(C, Ah[0], Ah[1], Ah[2], Ah[3], B0h, B1h);
            mma_bf16(C, Ah[0], Ah[1], Ah[2], Ah[3], B0l, B1l);
            mma_bf16(C, Al[0], Al[1], Al[2], Al[3], B0h, B1h);
        }
    }
}

__global__ void __launch_bounds__(THREADS, 1)
edge_mlp_mma(const float* __restrict__ src, const float* __restrict__ edg,
             const float* __restrict__ W1,  const float* __restrict__ b1,
             const float* __restrict__ gam, const float* __restrict__ bet,
             const float* __restrict__ W2,  const float* __restrict__ b2,
             float* __restrict__ out, int E, int ntiles) {
    extern __shared__ char smc[];
    const u32 sb = smem_u32(smc);
    const int tid = threadIdx.x;
    const int warp = tid >> 5, lane = tid & 31;
    const int wm = warp >> 2, wn = warp & 3;       // warp tile: rows wm*32, cols wn*32
    const int g = lane >> 2, tig = lane & 3;

    // ---- one-time: split weights hi/lo into [n][k] swizzled tiles ----
    for (int i = tid; i < 192 * 128; i += THREADS) {
        const int k = i >> 7, n = i & 127;
        u16 h, l;
        split2(W1[i], h, l);
        if (k < 128) {
            const u32 byte = ((n * 16 + ((k >> 3) ^ (n & 7))) << 4) + ((k & 7) << 1);
            *(u16*)(smc + OFF_W1AH + byte) = h;
            *(u16*)(smc + OFF_W1AL + byte) = l;
        } else {
            const int k2 = k - 128;
            const u32 byte = ((n * 8 + ((k2 >> 3) ^ (n & 7))) << 4) + ((k2 & 7) << 1);
            *(u16*)(smc + OFF_W1BH + byte) = h;
            *(u16*)(smc + OFF_W1BL + byte) = l;
        }
    }
    for (int i = tid; i < 128 * 128; i += THREADS) {
        const int k = i >> 7, n = i & 127;
        u16 h, l;
        split2(W2[i], h, l);
        const u32 byte = ((n * 16 + ((k >> 3) ^ (n & 7))) << 4) + ((k & 7) << 1);
        *(u16*)(smc + OFF_W2H + byte) = h;
        *(u16*)(smc + OFF_W2L + byte) = l;
    }
    if (tid < 128) {
        ((float*)(smc + OFF_B1))[tid] = b1[tid];
        ((float*)(smc + OFF_B2))[tid] = b2[tid];
        ((float*)(smc + OFF_G))[tid]  = gam[tid];
        ((float*)(smc + OFF_BT))[tid] = bet[tid];
    }
    const float* b1f = (const float*)(smc + OFF_B1);
    const float* b2f = (const float*)(smc + OFF_B2);
    const float* gf  = (const float*)(smc + OFF_G);
    const float* btf = (const float*)(smc + OFF_BT);

    for (int tile = blockIdx.x; tile < ntiles; tile += gridDim.x) {
        const int rowbase = tile * BR;
        const bool full = (rowbase + BR <= E);

        __syncthreads();   // BUF free (also orders weight preload on iter 0)

        // ---- stage src chunk (128x128 fp32 -> bf16 hi/lo, swizzled) ----
        {
            const float4* s4 = (const float4*)(src + (size_t)rowbase * NODE);
#pragma unroll
            for (int j = 0; j < (BR * NODE / 4) / THREADS; j++) {
                const int i = tid + j * THREADS;
                const int r = i >> 5, c4 = i & 31;
                float4 v = make_float4(0.f, 0.f, 0.f, 0.f);
                if (full || rowbase + r < E) v = s4[i];
                u16 h0, l0, h1, l1, h2, l2, h3, l3;
                split2(v.x, h0, l0); split2(v.y, h1, l1);
                split2(v.z, h2, l2); split2(v.w, h3, l3);
                const u32 byte = ((r * 16 + ((c4 >> 1) ^ (r & 7))) << 4) + ((c4 & 1) << 3);
                *(u64*)(smc + OFF_BUFH + byte) =
                    (u64)(h0 | ((u32)h1 << 16)) | ((u64)(h2 | ((u32)h3 << 16)) << 32);
                *(u64*)(smc + OFF_BUFL + byte) =
                    (u64)(l0 | ((u32)l1 << 16)) | ((u64)(l2 | ((u32)l3 << 16)) << 32);
            }
        }
        __syncthreads();

        // ---- GEMM1 part A: src x W1[k<128] ----
        float acc[2][4][4];
#pragma unroll
        for (int mt = 0; mt < 2; mt++)
#pragma unroll
            for (int nt = 0; nt < 4; nt++)
#pragma unroll
                for (int q = 0; q < 4; q++) acc[mt][nt][q] = 0.f;
#pragma unroll 2
        for (int ks = 0; ks < 8; ks++)
            k_step<16, 16>(sb + OFF_BUFH, sb + OFF_BUFL,
                           sb + OFF_W1AH, sb + OFF_W1AL, wm, wn, ks * 16, acc, lane);
        __syncthreads();   // src reads done

        // ---- stage edge chunk (128x64) ----
        {
            const float4* s4 = (const float4*)(edg + (size_t)rowbase * EDGED);
#pragma unroll
            for (int j = 0; j < (BR * EDGED / 4) / THREADS; j++) {
                const int i = tid + j * THREADS;
                const int r = i >> 4, c4 = i & 15;
                float4 v = make_float4(0.f, 0.f, 0.f, 0.f);
                if (full || rowbase + r < E) v = s4[i];
                u16 h0, l0, h1, l1, h2, l2, h3, l3;
                split2(v.x, h0, l0); split2(v.y, h1, l1);
                split2(v.z, h2, l2); split2(v.w, h3, l3);
                const u32 byte = ((r * 8 + ((c4 >> 1) ^ (r & 7))) << 4) + ((c4 & 1) << 3);
                *(u64*)(smc + OFF_BUFH + byte) =
                    (u64)(h0 | ((u32)h1 << 16)) | ((u64)(h2 | ((u32)h3 << 16)) << 32);
                *(u64*)(smc + OFF_BUFL + byte) =
                    (u64)(l0 | ((u32)l1 << 16)) | ((u64)(l2 | ((u32)l3 << 16)) << 32);
            }
        }
        __syncthreads();

        // ---- GEMM1 part B: edge x W1[k>=128] ----
#pragma unroll 2
        for (int ks = 0; ks < 4; ks++)
            k_step<8, 8>(sb + OFF_BUFH, sb + OFF_BUFL,
                         sb + OFF_W1BH, sb + OFF_W1BL, wm, wn, ks * 16, acc, lane);
        __syncthreads();   // edge reads done; BUF free for partials

        // ---- bias + LN partial sums (thread covers 4 rows x 8 cols) ----
        float s1[4] = {0.f, 0.f, 0.f, 0.f}, s2[4] = {0.f, 0.f, 0.f, 0.f};
#pragma unroll
        for (int mt = 0; mt < 2; mt++)
#pragma unroll
            for (int nt = 0; nt < 4; nt++) {
                const int c0 = wn * 32 + nt * 8 + 2 * tig;
                float* C = acc[mt][nt];
                C[0] += b1f[c0]; C[1] += b1f[c0 + 1];
                C[2] += b1f[c0]; C[3] += b1f[c0 + 1];
                s1[2 * mt]     += C[0] + C[1];
                s2[2 * mt]     += C[0] * C[0] + C[1] * C[1];
                s1[2 * mt + 1] += C[2] + C[3];
                s2[2 * mt + 1] += C[2] * C[2] + C[3] * C[3];
            }
#pragma unroll
        for (int j = 0; j < 4; j++) {
            s1[j] += __shfl_xor_sync(0xffffffffu, s1[j], 1);
            s1[j] += __shfl_xor_sync(0xffffffffu, s1[j], 2);
            s2[j] += __shfl_xor_sync(0xffffffffu, s2[j], 1);
            s2[j] += __shfl_xor_sync(0xffffffffu, s2[j], 2);
        }
        float2* part = (float2*)(smc + OFF_BUFH);
        if (tig == 0) {
#pragma unroll
            for (int j = 0; j < 4; j++) {
                const int row = wm * 32 + ((j >> 1) << 4) + ((j & 1) << 3) + g;
                part[row * 4 + wn] = make_float2(s1[j], s2[j]);
            }
        }
        __syncthreads();

        float mus[4], rss[4];
#pragma unroll
        for (int j = 0; j < 4; j++) {
            const int row = wm * 32 + ((j >> 1) << 4) + ((j & 1) << 3) + g;
            const float2 q0 = part[row * 4 + 0], q1 = part[row * 4 + 1];
            const float2 q2 = part[row * 4 + 2], q3 = part[row * 4 + 3];
            const float m1 = (q0.x + q1.x + q2.x + q3.x) * (1.0f / 128.0f);
            const float m2 = (q0.y + q1.y + q2.y + q3.y) * (1.0f / 128.0f);
            mus[j] = m1;
            rss[j] = rsqrtf(m2 - m1 * m1 + 1e-5f);
        }
        __syncthreads();   // partials consumed; BUF writable as H

        // ---- LN apply + SiLU + split -> H (bf16 hi/lo, swizzled) ----
#pragma unroll
        for (int mt = 0; mt < 2; mt++)
#pragma unroll
            for (int nt = 0; nt < 4; nt++) {
                const int c0 = wn * 32 + nt * 8 + 2 * tig;
                float* C = acc[mt][nt];
#pragma unroll
                for (int h = 0; h < 2; h++) {
                    const int j = 2 * mt + h;
                    const int row = wm * 32 + mt * 16 + h * 8 + g;
                    const float y0 = (C[2 * h + 0] - mus[j]) * rss[j] * gf[c0]     + btf[c0];
                    const float y1 = (C[2 * h + 1] - mus[j]) * rss[j] * gf[c0 + 1] + btf[c0 + 1];
                    u16 h0, l0, h1, l1;
                    split2(silu_f(y0), h0, l0);
                    split2(silu_f(y1), h1, l1);
                    const u32 byte = ((row * 16 + ((c0 >> 3) ^ (row & 7))) << 4)
                                   + ((c0 & 7) << 1);
                    *(u32*)(smc + OFF_BUFH + byte) = (u32)h0 | ((u32)h1 << 16);
                    *(u32*)(smc + OFF_BUFL + byte) = (u32)l0 | ((u32)l1 << 16);
                }
            }
        __syncthreads();

        // ---- GEMM2: H x W2 ----
#pragma unroll
        for (int mt = 0; mt < 2; mt++)
#pragma unroll
            for (int nt = 0; nt < 4; nt++)
#pragma unroll
                for (int q = 0; q < 4; q++) acc[mt][nt][q] = 0.f;
#pragma unroll 2
        for (int ks = 0; ks < 8; ks++)
            k_step<16, 16>(sb + OFF_BUFH, sb + OFF_BUFL,
                           sb + OFF_W2H, sb + OFF_W2L, wm, wn, ks * 16, acc, lane);

        // ---- epilogue: bias + SiLU + store ----
#pragma unroll
        for (int mt = 0; mt < 2; mt++)
#pragma unroll
            for (int nt = 0; nt < 4; nt++) {
                const int c0 = wn * 32 + nt * 8 + 2 * tig;
                float* C = acc[mt][nt];
#pragma unroll
                for (int h = 0; h < 2; h++) {
                    const int row = rowbase + wm * 32 + mt * 16 + h * 8 + g;
                    if (row < E) {
                        float2 o;
                        o.x = silu_f(C[2 * h + 0] + b2f[c0]);
                        o.y = silu_f(C[2 * h + 1] + b2f[c0 + 1]);
                        *(float2*)(out + (size_t)row * OUTD + c0) = o;
                    }
                }
            }
        // loop-top sync protects BUF before next staging
    }
}

extern "C" void kernel_launch(void* const* d_in, const int* in_sizes, int n_in,
                              void* d_out, int out_size) {
    const float* src = (const float*)d_in[0];
    const float* edg = (const float*)d_in[1];
    const float* W1  = (const float*)d_in[2];
    const float* b1  = (const float*)d_in[3];
    const float* gam = (const float*)d_in[4];
    const float* bet = (const float*)d_in[5];
    const float* W2  = (const float*)d_in[6];
    const float* b2  = (const float*)d_in[7];
    float* out = (float*)d_out;

    const int E = in_sizes[0] / NODE;
    const int ntiles = (E + BR - 1) / BR;

    cudaFuncSetAttribute(edge_mlp_mma,
                         cudaFuncAttributeMaxDynamicSharedMemorySize, SMEM_BYTES);

    int nsm = 148;
    if (cudaDeviceGetAttribute(&nsm, cudaDevAttrMultiProcessorCount, 0) != cudaSuccess
        || nsm <= 0)
        nsm = 148;
    const int grid = nsm < ntiles ? nsm : ntiles;

    edge_mlp_mma<<<grid, THREADS, SMEM_BYTES>>>(src, edg, W1, b1, gam, bet,
                                                W2, b2, out, E, ntiles);
}

// round 10
// speedup vs baseline: 3.3953x; 1.0786x over previous
#include <cuda_runtime.h>
#include <cuda_bf16.h>

// EdgeMLP via split-bf16 warp-level MMA (mma.sync m16n8k16, bf16->f32).
// out = silu( silu( LN( [src|edge] @ W1 + b1 ) ) @ W2 + b2 ), fp32 I/O.
// x = xh + xl (truncated-bf16 hi + bf16 residual);
// x*w ~= xh*wh + xh*wl + xl*wh (dropped xl*wl ~ 2^-16).
// v2: cp.async prefetch of next tile's raw src into BUF (overlaps epilogue),
// PRMT/bf16x2-based split packing (half the conversion ops).

typedef unsigned int u32;
typedef unsigned short u16;
typedef unsigned long long u64;

static constexpr int THREADS = 512;
static constexpr int BR = 128, NODE = 128, EDGED = 64, OUTD = 128;

// ---- smem byte offsets ----
static constexpr int OFF_W1AH = 0;        // W1 k<128:  [n=128][k=128] bf16 hi
static constexpr int OFF_W1AL = 32768;
static constexpr int OFF_W1BH = 65536;    // W1 k>=128: [128][64]
static constexpr int OFF_W1BL = 81920;
static constexpr int OFF_W2H  = 98304;    // [128][128]
static constexpr int OFF_W2L  = 131072;
static constexpr int OFF_BUFH = 163840;   // X/H hi; also raw-src cp.async target
static constexpr int OFF_BUFL = 196608;   //   first 4KB of BUFH doubles as LN partials
static constexpr int OFF_B1 = 229376, OFF_B2 = 229888;
static constexpr int OFF_G  = 230400, OFF_BT = 230912;
static constexpr int SMEM_BYTES = 231424; // <= 232448

__device__ __forceinline__ u32 smem_u32(const void* p) {
    u32 a;
    asm("{ .reg .u64 t; cvta.to.shared.u64 t, %1; cvt.u32.u64 %0, t; }"
        : "=r"(a) : "l"(p));
    return a;
}
__device__ __forceinline__ float silu_f(float y) {
    return __fdividef(y, 1.0f + __expf(-y));
}
// hi16(a) in low half, hi16(b) in high half (truncation split)
__device__ __forceinline__ u32 pack_hi2(float a, float b) {
    return __byte_perm(__float_as_uint(a), __float_as_uint(b), 0x7632);
}
// bf16(residual(a)) low, bf16(residual(b)) high
__device__ __forceinline__ u32 pack_lo2(float a, float b) {
    const float ra = a - __uint_as_float(__float_as_uint(a) & 0xFFFF0000u);
    const float rb = b - __uint_as_float(__float_as_uint(b) & 0xFFFF0000u);
    u32 r;
    asm("cvt.rn.bf16x2.f32 %0, %1, %2;" : "=r"(r) : "f"(rb), "f"(ra));
    return r;
}
__device__ __forceinline__ void cp16(u32 dst, const void* gsrc) {
    asm volatile("cp.async.ca.shared.global [%0], [%1], 16;"
                 :: "r"(dst), "l"(gsrc) : "memory");
}
#define CP_COMMIT() asm volatile("cp.async.commit_group;" ::: "memory")
#define CP_WAIT0()  asm volatile("cp.async.wait_group 0;" ::: "memory")

// byte address of 16B chunk holding (row, k) in a [rows][NC*8 k] bf16 tile,
// chunk-swizzled: chunk ^ (row & 7)  -> ldmatrix phases are conflict-free.
template <int NC>
__device__ __forceinline__ u32 fr_addr(u32 base, int row, int k) {
    return base + (((row * NC) + ((k >> 3) ^ (row & 7))) << 4);
}

#define LDSM4(R0, R1, R2, R3, A)                                          \
    asm volatile("ldmatrix.sync.aligned.m8n8.x4.shared.b16 {%0,%1,%2,%3}, [%4];" \
                 : "=r"(R0), "=r"(R1), "=r"(R2), "=r"(R3) : "r"(A))

__device__ __forceinline__ void mma_bf16(float* c, u32 a0, u32 a1, u32 a2, u32 a3,
                                         u32 b0, u32 b1) {
    asm volatile(
        "mma.sync.aligned.m16n8k16.row.col.f32.bf16.bf16.f32 "
        "{%0,%1,%2,%3}, {%4,%5,%6,%7}, {%8,%9}, {%0,%1,%2,%3};"
        : "+f"(c[0]), "+f"(c[1]), "+f"(c[2]), "+f"(c[3])
        : "r"(a0), "r"(a1), "r"(a2), "r"(a3), "r"(b0), "r"(b1));
}

// One k16 step: acc[2 mtiles][4 ntiles][4] += A(32xk16) x B(k16x32), 3 split terms.
template <int NCA, int NCB>
__device__ __forceinline__ void k_step(u32 aH, u32 aL, u32 bH, u32 bL,
                                       int wm, int wn, int k0,
                                       float acc[2][4][4], int lane) {
    const int la7 = lane & 7;
    const int arow = wm * 32 + la7 + (((lane >> 3) & 1) << 3);
    const int ak   = k0 + ((lane >> 4) << 3);
    const int brow = wn * 32 + la7 + ((lane >> 4) << 3);
    const int bk   = k0 + (((lane >> 3) & 1) << 3);

    u32 ah[8], al[8], bh[8], bl[8];
    LDSM4(ah[0], ah[1], ah[2], ah[3], fr_addr<NCA>(aH, arow, ak));
    LDSM4(ah[4], ah[5], ah[6], ah[7], fr_addr<NCA>(aH, arow + 16, ak));
    LDSM4(al[0], al[1], al[2], al[3], fr_addr<NCA>(aL, arow, ak));
    LDSM4(al[4], al[5], al[6], al[7], fr_addr<NCA>(aL, arow + 16, ak));
    LDSM4(bh[0], bh[1], bh[2], bh[3], fr_addr<NCB>(bH, brow, bk));
    LDSM4(bh[4], bh[5], bh[6], bh[7], fr_addr<NCB>(bH, brow + 16, bk));
    LDSM4(bl[0], bl[1], bl[2], bl[3], fr_addr<NCB>(bL, brow, bk));
    LDSM4(bl[4], bl[5], bl[6], bl[7], fr_addr<NCB>(bL, brow + 16, bk));

#pragma unroll
    for (int mt = 0; mt < 2; mt++) {
        const u32* Ah = ah + 4 * mt;
        const u32* Al = al + 4 * mt;
#pragma unroll
        for (int nt = 0; nt < 4; nt++) {
            const u32 B0h = bh[2 * nt], B1h = bh[2 * nt + 1];
            const u32 B0l = bl[2 * nt], B1l = bl[2 * nt + 1];
            float* C = acc[mt][nt];
            mma_bf16(C, Ah[0], Ah[1], Ah[2], Ah[3], B0h, B1h);
            mma_bf16(C, Ah[0], Ah[1], Ah[2], Ah[3], B0l, B1l);
            mma_bf16(C, Al[0], Al[1], Al[2], Al[3], B0h, B1h);
        }
    }
}

__global__ void __launch_bounds__(THREADS, 1)
edge_mlp_mma(const float* __restrict__ src, const float* __restrict__ edg,
             const float* __restrict__ W1,  const float* __restrict__ b1,
             const float* __restrict__ gam, const float* __restrict__ bet,
             const float* __restrict__ W2,  const float* __restrict__ b2,
             float* __restrict__ out, int E, int ntiles) {
    extern __shared__ char smc[];
    const u32 sb = smem_u32(smc);
    const int tid = threadIdx.x;
    const int warp = tid >> 5, lane = tid & 31;
    const int wm = warp >> 2, wn = warp & 3;       // warp tile: rows wm*32, cols wn*32
    const int g = lane >> 2, tig = lane & 3;

    // ---- prefetch first tile's raw src while weights get split ----
    {
        const int rowbase = blockIdx.x * BR;
        const float4* s4 = (const float4*)(src + (size_t)rowbase * NODE);
#pragma unroll
        for (int j = 0; j < 8; j++) {
            const int i = tid + j * THREADS;
            const int r = i >> 5;
            if (rowbase + r < E) cp16(sb + OFF_BUFH + (i << 4), s4 + i);
            else *(float4*)(smc + OFF_BUFH + (i << 4)) = make_float4(0.f, 0.f, 0.f, 0.f);
        }
        CP_COMMIT();
    }

    // ---- one-time: split weights hi/lo into [n][k] swizzled tiles ----
    for (int i = tid; i < 192 * 128; i += THREADS) {
        const int k = i >> 7, n = i & 127;
        const float w = W1[i];
        const u32 h = pack_hi2(w, 0.f) & 0xFFFFu;
        const u32 l = pack_lo2(w, 0.f) & 0xFFFFu;
        if (k < 128) {
            const u32 byte = ((n * 16 + ((k >> 3) ^ (n & 7))) << 4) + ((k & 7) << 1);
            *(u16*)(smc + OFF_W1AH + byte) = (u16)h;
            *(u16*)(smc + OFF_W1AL + byte) = (u16)l;
        } else {
            const int k2 = k - 128;
            const u32 byte = ((n * 8 + ((k2 >> 3) ^ (n & 7))) << 4) + ((k2 & 7) << 1);
            *(u16*)(smc + OFF_W1BH + byte) = (u16)h;
            *(u16*)(smc + OFF_W1BL + byte) = (u16)l;
        }
    }
    for (int i = tid; i < 128 * 128; i += THREADS) {
        const int k = i >> 7, n = i & 127;
        const float w = W2[i];
        const u32 byte = ((n * 16 + ((k >> 3) ^ (n & 7))) << 4) + ((k & 7) << 1);
        *(u16*)(smc + OFF_W2H + byte) = (u16)(pack_hi2(w, 0.f) & 0xFFFFu);
        *(u16*)(smc + OFF_W2L + byte) = (u16)(pack_lo2(w, 0.f) & 0xFFFFu);
    }
    if (tid < 128) {
        ((float*)(smc + OFF_B1))[tid] = b1[tid];
        ((float*)(smc + OFF_B2))[tid] = b2[tid];
        ((float*)(smc + OFF_G))[tid]  = gam[tid];
        ((float*)(smc + OFF_BT))[tid] = bet[tid];
    }
    const float* b1f = (const float*)(smc + OFF_B1);
    const float* b2f = (const float*)(smc + OFF_B2);
    const float* gf  = (const float*)(smc + OFF_G);
    const float* btf = (const float*)(smc + OFF_BT);

    for (int tile = blockIdx.x; tile < ntiles; tile += gridDim.x) {
        const int rowbase = tile * BR;
        const bool full = (rowbase + BR <= E);

        // ---- convert prefetched raw src (in BUF) -> bf16 hi/lo, in place ----
        CP_WAIT0();
        __syncthreads();   // all threads' cp.async data landed; weights ready (iter 0)
        {
            float4 xa[8];
#pragma unroll
            for (int j = 0; j < 8; j++)
                xa[j] = *(const float4*)(smc + OFF_BUFH + ((tid + j * THREADS) << 4));
            __syncthreads();   // all raw reads complete before overwriting
#pragma unroll
            for (int j = 0; j < 8; j++) {
                const int i = tid + j * THREADS;
                const int r = i >> 5, c4 = i & 31;
                const float4 v = xa[j];
                const u32 byte = ((r * 16 + ((c4 >> 1) ^ (r & 7))) << 4) + ((c4 & 1) << 3);
                *(u64*)(smc + OFF_BUFH + byte) =
                    (u64)pack_hi2(v.x, v.y) | ((u64)pack_hi2(v.z, v.w) << 32);
                *(u64*)(smc + OFF_BUFL + byte) =
                    (u64)pack_lo2(v.x, v.y) | ((u64)pack_lo2(v.z, v.w) << 32);
            }
        }
        __syncthreads();

        // ---- GEMM1 part A: src x W1[k<128] ----
        float acc[2][4][4];
#pragma unroll
        for (int mt = 0; mt < 2; mt++)
#pragma unroll
            for (int nt = 0; nt < 4; nt++)
#pragma unroll
                for (int q = 0; q < 4; q++) acc[mt][nt][q] = 0.f;
#pragma unroll 2
        for (int ks = 0; ks < 8; ks++)
            k_step<16, 16>(sb + OFF_BUFH, sb + OFF_BUFL,
                           sb + OFF_W1AH, sb + OFF_W1AL, wm, wn, ks * 16, acc, lane);
        __syncthreads();   // src reads done

        // ---- stage edge chunk (128x64, direct LDG) ----
        {
            const float4* s4 = (const float4*)(edg + (size_t)rowbase * EDGED);
#pragma unroll
            for (int j = 0; j < (BR * EDGED / 4) / THREADS; j++) {
                const int i = tid + j * THREADS;
                const int r = i >> 4, c4 = i & 15;
                float4 v = make_float4(0.f, 0.f, 0.f, 0.f);
                if (full || rowbase + r < E) v = s4[i];
                const u32 byte = ((r * 8 + ((c4 >> 1) ^ (r & 7))) << 4) + ((c4 & 1) << 3);
                *(u64*)(smc + OFF_BUFH + byte) =
                    (u64)pack_hi2(v.x, v.y) | ((u64)pack_hi2(v.z, v.w) << 32);
                *(u64*)(smc + OFF_BUFL + byte) =
                    (u64)pack_lo2(v.x, v.y) | ((u64)pack_lo2(v.z, v.w) << 32);
            }
        }
        __syncthreads();

        // ---- GEMM1 part B: edge x W1[k>=128] ----
#pragma unroll 2
        for (int ks = 0; ks < 4; ks++)
            k_step<8, 8>(sb + OFF_BUFH, sb + OFF_BUFL,
                         sb + OFF_W1BH, sb + OFF_W1BL, wm, wn, ks * 16, acc, lane);
        __syncthreads();   // edge reads done; BUF free for partials

        // ---- bias + LN partial sums (thread covers 4 rows x 8 cols) ----
        float s1[4] = {0.f, 0.f, 0.f, 0.f}, s2[4] = {0.f, 0.f, 0.f, 0.f};
#pragma unroll
        for (int mt = 0; mt < 2; mt++)
#pragma unroll
            for (int nt = 0; nt < 4; nt++) {
                const int c0 = wn * 32 + nt * 8 + 2 * tig;
                float* C = acc[mt][nt];
                C[0] += b1f[c0]; C[1] += b1f[c0 + 1];
                C[2] += b1f[c0]; C[3] += b1f[c0 + 1];
                s1[2 * mt]     += C[0] + C[1];
                s2[2 * mt]     += C[0] * C[0] + C[1] * C[1];
                s1[2 * mt + 1] += C[2] + C[3];
                s2[2 * mt + 1] += C[2] * C[2] + C[3] * C[3];
            }
#pragma unroll
        for (int j = 0; j < 4; j++) {
            s1[j] += __shfl_xor_sync(0xffffffffu, s1[j], 1);
            s1[j] += __shfl_xor_sync(0xffffffffu, s1[j], 2);
            s2[j] += __shfl_xor_sync(0xffffffffu, s2[j], 1);
            s2[j] += __shfl_xor_sync(0xffffffffu, s2[j], 2);
        }
        float2* part = (float2*)(smc + OFF_BUFH);
        if (tig == 0) {
#pragma unroll
            for (int j = 0; j < 4; j++) {
                const int row = wm * 32 + ((j >> 1) << 4) + ((j & 1) << 3) + g;
                part[row * 4 + wn] = make_float2(s1[j], s2[j]);
            }
        }
        __syncthreads();

        float mus[4], rss[4];
#pragma unroll
        for (int j = 0; j < 4; j++) {
            const int row = wm * 32 + ((j >> 1) << 4) + ((j & 1) << 3) + g;
            const float2 q0 = part[row * 4 + 0], q1 = part[row * 4 + 1];
            const float2 q2 = part[row * 4 + 2], q3 = part[row * 4 + 3];
            const float m1 = (q0.x + q1.x + q2.x + q3.x) * (1.0f / 128.0f);
            const float m2 = (q0.y + q1.y + q2.y + q3.y) * (1.0f / 128.0f);
            mus[j] = m1;
            rss[j] = rsqrtf(m2 - m1 * m1 + 1e-5f);
        }
        __syncthreads();   // partials consumed; BUF writable as H

        // ---- LN apply + SiLU + split -> H (bf16 hi/lo, swizzled) ----
#pragma unroll
        for (int mt = 0; mt < 2; mt++)
#pragma unroll
            for (int nt = 0; nt < 4; nt++) {
                const int c0 = wn * 32 + nt * 8 + 2 * tig;
                float* C = acc[mt][nt];
#pragma unroll
                for (int h = 0; h < 2; h++) {
                    const int j = 2 * mt + h;
                    const int row = wm * 32 + mt * 16 + h * 8 + g;
                    const float y0 = silu_f((C[2 * h + 0] - mus[j]) * rss[j] * gf[c0]     + btf[c0]);
                    const float y1 = silu_f((C[2 * h + 1] - mus[j]) * rss[j] * gf[c0 + 1] + btf[c0 + 1]);
                    const u32 byte = ((row * 16 + ((c0 >> 3) ^ (row & 7))) << 4)
                                   + ((c0 & 7) << 1);
                    *(u32*)(smc + OFF_BUFH + byte) = pack_hi2(y0, y1);
                    *(u32*)(smc + OFF_BUFL + byte) = pack_lo2(y0, y1);
                }
            }
        __syncthreads();

        // ---- GEMM2: H x W2 ----
#pragma unroll
        for (int mt = 0; mt < 2; mt++)
#pragma unroll
            for (int nt = 0; nt < 4; nt++)
#pragma unroll
                for (int q = 0; q < 4; q++) acc[mt][nt][q] = 0.f;
#pragma unroll 2
        for (int ks = 0; ks < 8; ks++)
            k_step<16, 16>(sb + OFF_BUFH, sb + OFF_BUFL,
                           sb + OFF_W2H, sb + OFF_W2L, wm, wn, ks * 16, acc, lane);
        __syncthreads();   // all warps done reading BUF(H)

        // ---- prefetch next tile's raw src into BUF (overlaps epilogue) ----
        {
            const int ntile = tile + gridDim.x;
            if (ntile < ntiles) {
                const int nrb = ntile * BR;
                const float4* s4 = (const float4*)(src + (size_t)nrb * NODE);
#pragma unroll
                for (int j = 0; j < 8; j++) {
                    const int i = tid + j * THREADS;
                    const int r = i >> 5;
                    if (nrb + r < E) cp16(sb + OFF_BUFH + (i << 4), s4 + i);
                    else *(float4*)(smc + OFF_BUFH + (i << 4)) =
                             make_float4(0.f, 0.f, 0.f, 0.f);
                }
            }
            CP_COMMIT();
        }

        // ---- epilogue: bias + SiLU + store ----
#pragma unroll
        for (int mt = 0; mt < 2; mt++)
#pragma unroll
            for (int nt = 0; nt < 4; nt++) {
                const int c0 = wn * 32 + nt * 8 + 2 * tig;
                float* C = acc[mt][nt];
#pragma unroll
                for (int h = 0; h < 2; h++) {
                    const int row = rowbase + wm * 32 + mt * 16 + h * 8 + g;
                    if (row < E) {
                        float2 o;
                        o.x = silu_f(C[2 * h + 0] + b2f[c0]);
                        o.y = silu_f(C[2 * h + 1] + b2f[c0 + 1]);
                        *(float2*)(out + (size_t)row * OUTD + c0) = o;
                    }
                }
            }
    }
}

extern "C" void kernel_launch(void* const* d_in, const int* in_sizes, int n_in,
                              void* d_out, int out_size) {
    const float* src = (const float*)d_in[0];
    const float* edg = (const float*)d_in[1];
    const float* W1  = (const float*)d_in[2];
    const float* b1  = (const float*)d_in[3];
    const float* gam = (const float*)d_in[4];
    const float* bet = (const float*)d_in[5];
    const float* W2  = (const float*)d_in[6];
    const float* b2  = (const float*)d_in[7];
    float* out = (float*)d_out;

    const int E = in_sizes[0] / NODE;
    const int ntiles = (E + BR - 1) / BR;

    cudaFuncSetAttribute(edge_mlp_mma,
                         cudaFuncAttributeMaxDynamicSharedMemorySize, SMEM_BYTES);

    int nsm = 148;
    if (cudaDeviceGetAttribute(&nsm, cudaDevAttrMultiProcessorCount, 0) != cudaSuccess
        || nsm <= 0)
        nsm = 148;
    const int grid = nsm < ntiles ? nsm : ntiles;

    edge_mlp_mma<<<grid, THREADS, SMEM_BYTES>>>(src, edg, W1, b1, gam, bet,
                                                W2, b2, out, E, ntiles);
}